// round 15
// baseline (speedup 1.0000x reference)
#include <cuda_runtime.h>

typedef unsigned long long ull;

#define NT 320              // threads/CTA; NT/2 = 160 elements per CTA
#define NSTEPS 16
#define DT (1.0f/16.0f)
#define TRI(i,j) ((i)*7 - (i)*((i)-1)/2 + (j) - (i) - 1)

__device__ __forceinline__ ull fma2(ull a, ull b, ull c){
    ull d; asm("fma.rn.f32x2 %0,%1,%2,%3;" : "=l"(d) : "l"(a),"l"(b),"l"(c)); return d;
}
__device__ __forceinline__ ull mul2(ull a, ull b){
    ull d; asm("mul.rn.f32x2 %0,%1,%2;" : "=l"(d) : "l"(a),"l"(b)); return d;
}
__device__ __forceinline__ ull add2(ull a, ull b){
    ull d; asm("add.rn.f32x2 %0,%1,%2;" : "=l"(d) : "l"(a),"l"(b)); return d;
}
__device__ __forceinline__ ull sub2(ull a, ull b){
    ull d; asm("sub.rn.f32x2 %0,%1,%2;" : "=l"(d) : "l"(a),"l"(b)); return d;
}
__device__ __forceinline__ float hsum2(ull a){
    float lo,hi; asm("mov.b64 {%0,%1},%2;" : "=f"(lo),"=f"(hi) : "l"(a)); return lo+hi;
}
__device__ __forceinline__ ull dup_f(float x){
    ull r; asm("mov.b64 %0,{%1,%1};" : "=l"(r) : "f"(x)); return r;
}
__device__ __forceinline__ ull dup_lo(ull a){
    ull r; asm("{.reg .f32 l,h; mov.b64 {l,h},%1; mov.b64 %0,{l,l};}" : "=l"(r) : "l"(a)); return r;
}
__device__ __forceinline__ ull dup_hi(ull a){
    ull r; asm("{.reg .f32 l,h; mov.b64 {l,h},%1; mov.b64 %0,{h,h};}" : "=l"(r) : "l"(a)); return r;
}
__device__ __forceinline__ ull pack2(float lo, float hi){
    ull r; asm("mov.b64 %0,{%1,%2};" : "=l"(r) : "f"(lo),"f"(hi)); return r;
}
__device__ __forceinline__ void unp2(ull a, float& lo, float& hi){
    asm("mov.b64 {%0,%1},%2;" : "=f"(lo),"=f"(hi) : "l"(a));
}
// half-dot: 2 packed ulls per operand (4 floats each side)
__device__ __forceinline__ ull dot2(ull a0, ull a1, ull b0, ull b1){
    return fma2(a1, b1, mul2(a0, b0));
}
// exchange with pair partner (lane ^ 1)
__device__ __forceinline__ ull shflx_ull(ull x){
    unsigned lo = __shfl_xor_sync(0xffffffffu, (unsigned)x, 1);
    unsigned hi = __shfl_xor_sync(0xffffffffu, (unsigned)(x >> 32), 1);
    return (ull)lo | ((ull)hi << 32);
}
__device__ __forceinline__ float shflx_f(float x){
    return __shfl_xor_sync(0xffffffffu, x, 1);
}

extern "C" __global__ void __launch_bounds__(NT, 1)
adj_lie_kernel(const float* __restrict__ U0, const float* __restrict__ eps,
               const float* __restrict__ W0, const float* __restrict__ W1,
               const float* __restrict__ W2, float* __restrict__ out, int B)
{
    // Each ELEMENT split across a thread pair: h=0 owns cols 0-3, h=1 cols 4-7.
    // W2a = W2 - W2^T.
    //   F = w0a + t*w1a + 0.5*U*W2a*U^T
    //   r_ij = <Ue_j,v_i> - <Ue_i,v_j>;  z_i = Sum_j r_ij Ue_j (fused with vel)
    //   kl_unscaled = -Sum_i <z_i, gw_i>,  gw_j = W2a*v_j^T (constant)
    //   (sign folded into the final -0.5 factor at output)
    extern __shared__ ull shl[];
    ull* w2ac = shl;            // 32 : W2a column-packed [k][c], c=0..3
    ull* w01  = shl + 32;       // 28 : (w0a_ij, w1a_ij)
    ull* svb  = shl + 64;               // [16][NT] : my half of v rows
    ull* sgwb = svb  + 16*NT;           // [16][NT] : my half of gw rows
    ull* subb = sgwb + 16*NT;           // [16][NT] : my half of U base
    ull* sacb = subb + 16*NT;           // [16][NT] : my half of RK4 accum

    const int tid = threadIdx.x;
    const int h   = tid & 1;
    const int ge  = blockIdx.x * (NT/2) + (tid >> 1);

    if (tid < 32) {
        int k = tid >> 2, c = tid & 3;
        float a0 = W2[(2*c  )*8 + k] - W2[k*8 + (2*c  )];   // W2a[2c  ][k]
        float a1 = W2[(2*c+1)*8 + k] - W2[k*8 + (2*c+1)];   // W2a[2c+1][k]
        w2ac[tid] = pack2(a0, a1);
    }
    if (tid < 64) {
        int i = tid >> 3, j = tid & 7;
        if (i < j) {
            w01[TRI(i,j)] = pack2(0.5f * (W0[i*8+j] - W0[j*8+i]),
                                  0.5f * (W1[i*8+j] - W1[j*8+i]));
        }
    }
    __syncthreads();

    // 2*B is a multiple of 32 -> exits are warp-uniform (shfl-safe below)
    if (ge >= B) return;

    const ull* w2h = w2ac + 2*h;     // my 2 columns of each W2a k-row
    ull* sv  = svb  + tid;
    ull* sgw = sgwb + tid;
    ull* sub = subb + tid;
    ull* sac = sacb + tid;

    ull UeP[16];
    {
        const float* ub = U0  + (size_t)ge * 64 + h*4;
        const float* eb = eps + (size_t)ge * 64 + h*4;
        ull vr[16];
        #pragma unroll
        for (int r = 0; r < 8; r++) {
            ulonglong2 u = *(const ulonglong2*)(ub + r*8);
            UeP[r*2] = u.x; UeP[r*2+1] = u.y;
            sub[(r*2)*NT] = u.x; sub[(r*2+1)*NT] = u.y;
            ulonglong2 e = *(const ulonglong2*)(eb + r*8);
            vr[r*2] = e.x; vr[r*2+1] = e.y;
            sv[(r*2)*NT] = e.x; sv[(r*2+1)*NT] = e.y;
        }
        // gw_j = W2a * v_j^T  (my half), needs full v_j broadcast
        #pragma unroll
        for (int j = 0; j < 8; j++) {
            ull p0 = shflx_ull(vr[j*2]), p1 = shflx_ull(vr[j*2+1]);
            ull aa[4];
            aa[0] = h ? p0 : vr[j*2];       // cols 0,1
            aa[1] = h ? p1 : vr[j*2+1];     // cols 2,3
            aa[2] = h ? vr[j*2]   : p0;     // cols 4,5
            aa[3] = h ? vr[j*2+1] : p1;     // cols 6,7
            ull g0, g1;
            #pragma unroll
            for (int k = 0; k < 8; k++) {
                ull d = (k & 1) ? dup_hi(aa[k>>1]) : dup_lo(aa[k>>1]);
                if (k == 0) { g0 = mul2(d, w2h[0]);       g1 = mul2(d, w2h[1]); }
                else        { g0 = fma2(d, w2h[k*4+0], g0); g1 = fma2(d, w2h[k*4+1], g1); }
            }
            sgw[(j*2)*NT] = g0; sgw[(j*2+1)*NT] = g1;
        }
    }

    ull logjP = 0ull, laccP = 0ull;

    #pragma unroll 1
    for (int step = 0; step < NSTEPS; step++) {
        float t0 = (float)step * DT;
        #pragma unroll 1
        for (int s = 0; s < 4; s++) {
            float t = t0 + ((s == 0) ? 0.0f : (s == 3 ? DT : 0.5f*DT));

            float rv[28];
            float fv[28];

            // ===== pair loop, streamed Ga_j, j-outer: only r and f =====
            #pragma unroll
            for (int j = 1; j < 8; j++) {
                // full Ue_j broadcast (partner exchange + SEL merge)
                ull p0 = shflx_ull(UeP[j*2]), p1 = shflx_ull(UeP[j*2+1]);
                ull aa[4];
                aa[0] = h ? p0 : UeP[j*2];
                aa[1] = h ? p1 : UeP[j*2+1];
                aa[2] = h ? UeP[j*2]   : p0;
                aa[3] = h ? UeP[j*2+1] : p1;
                // Ga_j = W2a * Ue_j^T  (my half)
                ull ga0, ga1;
                #pragma unroll
                for (int k = 0; k < 8; k++) {
                    ull d = (k & 1) ? dup_hi(aa[k>>1]) : dup_lo(aa[k>>1]);
                    if (k == 0) { ga0 = mul2(d, w2h[0]);        ga1 = mul2(d, w2h[1]); }
                    else        { ga0 = fma2(d, w2h[k*4+0], ga0); ga1 = fma2(d, w2h[k*4+1], ga1); }
                }
                ull vj0 = sv[(j*2)*NT], vj1 = sv[(j*2+1)*NT];
                #pragma unroll
                for (int i = 0; i < j; i++) {
                    ull vi0 = sv[(i*2)*NT], vi1 = sv[(i*2+1)*NT];
                    // r = <Ue_j, v_i> - <Ue_i, v_j>   (full, via half + combine)
                    ull pr = sub2(dot2(UeP[j*2], UeP[j*2+1], vi0, vi1),
                                  dot2(UeP[i*2], UeP[i*2+1], vj0, vj1));
                    float rh = hsum2(pr);
                    rv[TRI(i,j)] = rh + shflx_f(rh);
                    // f = w0a + t*w1a + 0.5*<Ue_i, Ga_j>
                    ull pg = dot2(UeP[i*2], UeP[i*2+1], ga0, ga1);
                    float gh = hsum2(pg);
                    float g  = gh + shflx_f(gh);
                    float w0, w1; unp2(w01[TRI(i,j)], w0, w1);
                    fv[TRI(i,j)] = fmaf(t, w1, fmaf(0.5f, g, w0));
                }
            }

            // ===== fused vel + z rows, kl = Sum_i <z_i, gw_i> (my half) =====
            ull klP = 0ull;
            ull T[16];
            #pragma unroll
            for (int i = 0; i < 8; i++) {
                ull a0, a1, z0, z1;
                #pragma unroll
                for (int j = 0; j < 8; j++) {
                    if (j == i) continue;
                    const bool first = (j == ((i == 0) ? 1 : 0));
                    float f = (i < j) ? fv[TRI(i,j)] : -fv[TRI(j,i)];
                    float r = (i < j) ? rv[TRI(i,j)] : -rv[TRI(j,i)];
                    ull fd = dup_f(f);
                    ull rd = dup_f(r);
                    if (first) {
                        a0 = mul2(fd, UeP[j*2]);     a1 = mul2(fd, UeP[j*2+1]);
                        z0 = mul2(rd, UeP[j*2]);     z1 = mul2(rd, UeP[j*2+1]);
                    } else {
                        a0 = fma2(fd, UeP[j*2], a0); a1 = fma2(fd, UeP[j*2+1], a1);
                        z0 = fma2(rd, UeP[j*2], z0); z1 = fma2(rd, UeP[j*2+1], z1);
                    }
                }
                T[i*2] = a0; T[i*2+1] = a1;
                klP = add2(klP, dot2(z0, z1, sgw[(i*2)*NT], sgw[(i*2+1)*NT]));
            }

            // ===== RK4 stage update (kl kept packed per-half; sign at output) =====
            if (s == 0) {
                laccP = klP;
                const ull hdt = dup_f(0.5f*DT);
                #pragma unroll
                for (int c = 0; c < 16; c++) {
                    sac[c*NT] = T[c];
                    UeP[c] = fma2(hdt, T[c], UeP[c]);
                }
            } else if (s == 1) {
                const ull two = dup_f(2.0f), hdt = dup_f(0.5f*DT);
                laccP = fma2(two, klP, laccP);
                #pragma unroll
                for (int c = 0; c < 16; c++) {
                    sac[c*NT] = fma2(two, T[c], sac[c*NT]);
                    UeP[c] = fma2(hdt, T[c], sub[c*NT]);
                }
            } else if (s == 2) {
                const ull two = dup_f(2.0f), fdt = dup_f(DT);
                laccP = fma2(two, klP, laccP);
                #pragma unroll
                for (int c = 0; c < 16; c++) {
                    sac[c*NT] = fma2(two, T[c], sac[c*NT]);
                    UeP[c] = fma2(fdt, T[c], sub[c*NT]);
                }
            } else {
                const ull d6 = dup_f(DT/6.0f);
                logjP = fma2(d6, add2(laccP, klP), logjP);
                #pragma unroll
                for (int c = 0; c < 16; c++) {
                    ull un = fma2(d6, add2(sac[c*NT], T[c]), sub[c*NT]);
                    UeP[c] = un;
                    sub[c*NT] = un;
                }
            }
        }
    }

    // ---- outputs: U halves, then logj (pair-combined; kl sign gives -0.5) ----
    {
        float* ob = out + (size_t)ge * 64 + h*4;
        #pragma unroll
        for (int r = 0; r < 8; r++) {
            ulonglong2 w; w.x = UeP[r*2]; w.y = UeP[r*2+1];
            *(ulonglong2*)(ob + r*8) = w;
        }
        float lj = hsum2(logjP);
        lj += shflx_f(lj);
        if (h == 0) out[(size_t)B * 64 + ge] = -0.5f * lj;
    }
}

extern "C" void kernel_launch(void* const* d_in, const int* in_sizes, int n_in,
                              void* d_out, int out_size)
{
    const float* U0  = (const float*)d_in[0];
    const float* eps = (const float*)d_in[1];
    const float* W0  = (const float*)d_in[2];
    const float* W1  = (const float*)d_in[3];
    const float* W2  = (const float*)d_in[4];
    float* out = (float*)d_out;

    int B = in_sizes[0] / 64;
    size_t shmem = (size_t)(64 + 4 * 16 * NT) * sizeof(ull);   // ~164 KB
    cudaFuncSetAttribute(adj_lie_kernel,
                         cudaFuncAttributeMaxDynamicSharedMemorySize, (int)shmem);
    int grid = (B + NT/2 - 1) / (NT/2);
    adj_lie_kernel<<<grid, NT, shmem>>>(U0, eps, W0, W1, W2, out, B);
}

// round 16
// speedup vs baseline: 1.1302x; 1.1302x over previous
#include <cuda_runtime.h>

typedef unsigned long long ull;

#define NT 384              // threads/CTA; NT/2 = 192 elements per CTA
#define NSTEPS 16
#define DT (1.0f/16.0f)
#define TRI(i,j) ((i)*7 - (i)*((i)-1)/2 + (j) - (i) - 1)

__device__ __forceinline__ ull fma2(ull a, ull b, ull c){
    ull d; asm("fma.rn.f32x2 %0,%1,%2,%3;" : "=l"(d) : "l"(a),"l"(b),"l"(c)); return d;
}
__device__ __forceinline__ ull mul2(ull a, ull b){
    ull d; asm("mul.rn.f32x2 %0,%1,%2;" : "=l"(d) : "l"(a),"l"(b)); return d;
}
__device__ __forceinline__ ull add2(ull a, ull b){
    ull d; asm("add.rn.f32x2 %0,%1,%2;" : "=l"(d) : "l"(a),"l"(b)); return d;
}
__device__ __forceinline__ ull sub2(ull a, ull b){
    ull d; asm("sub.rn.f32x2 %0,%1,%2;" : "=l"(d) : "l"(a),"l"(b)); return d;
}
__device__ __forceinline__ float hsum2(ull a){
    float lo,hi; asm("mov.b64 {%0,%1},%2;" : "=f"(lo),"=f"(hi) : "l"(a)); return lo+hi;
}
__device__ __forceinline__ ull dup_f(float x){
    ull r; asm("mov.b64 %0,{%1,%1};" : "=l"(r) : "f"(x)); return r;
}
__device__ __forceinline__ ull dup_lo(ull a){
    ull r; asm("{.reg .f32 l,h; mov.b64 {l,h},%1; mov.b64 %0,{l,l};}" : "=l"(r) : "l"(a)); return r;
}
__device__ __forceinline__ ull dup_hi(ull a){
    ull r; asm("{.reg .f32 l,h; mov.b64 {l,h},%1; mov.b64 %0,{h,h};}" : "=l"(r) : "l"(a)); return r;
}
__device__ __forceinline__ ull pack2(float lo, float hi){
    ull r; asm("mov.b64 %0,{%1,%2};" : "=l"(r) : "f"(lo),"f"(hi)); return r;
}
__device__ __forceinline__ void unp2(ull a, float& lo, float& hi){
    asm("mov.b64 {%0,%1},%2;" : "=f"(lo),"=f"(hi) : "l"(a));
}
// half-dot: 2 packed ulls per operand (4 floats each side)
__device__ __forceinline__ ull dot2(ull a0, ull a1, ull b0, ull b1){
    return fma2(a1, b1, mul2(a0, b0));
}
// exchange with pair partner (lane ^ 1)
__device__ __forceinline__ ull shflx_ull(ull x){
    unsigned lo = __shfl_xor_sync(0xffffffffu, (unsigned)x, 1);
    unsigned hi = __shfl_xor_sync(0xffffffffu, (unsigned)(x >> 32), 1);
    return (ull)lo | ((ull)hi << 32);
}
__device__ __forceinline__ float shflx_f(float x){
    return __shfl_xor_sync(0xffffffffu, x, 1);
}

extern "C" __global__ void __launch_bounds__(NT, 1)
adj_lie_kernel(const float* __restrict__ U0, const float* __restrict__ eps,
               const float* __restrict__ W0, const float* __restrict__ W1,
               const float* __restrict__ W2, float* __restrict__ out, int B)
{
    // Each ELEMENT split across a thread pair: h=0 owns cols 0-3, h=1 cols 4-7.
    // W2a = W2 - W2^T.
    //   F = w0a + t*w1a + 0.5*U*W2a*U^T
    //   r_ij = <Ue_j,v_i> - <Ue_i,v_j>;  z_i = Sum_j r_ij Ue_j (fused with vel)
    //   kl_unscaled = -Sum_i <z_i, gw_i>,  gw_j = W2a*v_j^T (constant)
    //   (sign folded into the final -0.5 factor at output)
    extern __shared__ ull shl[];
    ull* w2ac = shl;            // 32 : W2a column-packed [k][c], c=0..3
    ull* w01  = shl + 32;       // 28 : (w0a_ij, w1a_ij)
    ull* svb  = shl + 64;               // [16][NT] : my half of v rows
    ull* sgwb = svb  + 16*NT;           // [16][NT] : my half of gw rows
    ull* subb = sgwb + 16*NT;           // [16][NT] : my half of U base
    ull* sacb = subb + 16*NT;           // [16][NT] : my half of RK4 accum

    const int tid = threadIdx.x;
    const int h   = tid & 1;
    const int ge  = blockIdx.x * (NT/2) + (tid >> 1);

    if (tid < 32) {
        int k = tid >> 2, c = tid & 3;
        float a0 = W2[(2*c  )*8 + k] - W2[k*8 + (2*c  )];   // W2a[2c  ][k]
        float a1 = W2[(2*c+1)*8 + k] - W2[k*8 + (2*c+1)];   // W2a[2c+1][k]
        w2ac[tid] = pack2(a0, a1);
    }
    if (tid < 64) {
        int i = tid >> 3, j = tid & 7;
        if (i < j) {
            w01[TRI(i,j)] = pack2(0.5f * (W0[i*8+j] - W0[j*8+i]),
                                  0.5f * (W1[i*8+j] - W1[j*8+i]));
        }
    }
    __syncthreads();

    // 2*B is a multiple of 32 -> exits are warp-uniform (shfl-safe below)
    if (ge >= B) return;

    const ull* w2h = w2ac + 2*h;     // my 2 columns of each W2a k-row
    ull* sv  = svb  + tid;
    ull* sgw = sgwb + tid;
    ull* sub = subb + tid;
    ull* sac = sacb + tid;

    ull UeP[16];
    {
        const float* ub = U0  + (size_t)ge * 64 + h*4;
        const float* eb = eps + (size_t)ge * 64 + h*4;
        ull vr[16];
        #pragma unroll
        for (int r = 0; r < 8; r++) {
            ulonglong2 u = *(const ulonglong2*)(ub + r*8);
            UeP[r*2] = u.x; UeP[r*2+1] = u.y;
            sub[(r*2)*NT] = u.x; sub[(r*2+1)*NT] = u.y;
            ulonglong2 e = *(const ulonglong2*)(eb + r*8);
            vr[r*2] = e.x; vr[r*2+1] = e.y;
            sv[(r*2)*NT] = e.x; sv[(r*2+1)*NT] = e.y;
        }
        // gw_j = W2a * v_j^T  (my half), needs full v_j broadcast
        #pragma unroll
        for (int j = 0; j < 8; j++) {
            ull p0 = shflx_ull(vr[j*2]), p1 = shflx_ull(vr[j*2+1]);
            ull aa[4];
            aa[0] = h ? p0 : vr[j*2];       // cols 0,1
            aa[1] = h ? p1 : vr[j*2+1];     // cols 2,3
            aa[2] = h ? vr[j*2]   : p0;     // cols 4,5
            aa[3] = h ? vr[j*2+1] : p1;     // cols 6,7
            ull g0, g1;
            #pragma unroll
            for (int k = 0; k < 8; k++) {
                ull d = (k & 1) ? dup_hi(aa[k>>1]) : dup_lo(aa[k>>1]);
                if (k == 0) { g0 = mul2(d, w2h[0]);       g1 = mul2(d, w2h[1]); }
                else        { g0 = fma2(d, w2h[k*4+0], g0); g1 = fma2(d, w2h[k*4+1], g1); }
            }
            sgw[(j*2)*NT] = g0; sgw[(j*2+1)*NT] = g1;
        }
    }

    ull logjP = 0ull, laccP = 0ull;

    #pragma unroll 1
    for (int step = 0; step < NSTEPS; step++) {
        float t0 = (float)step * DT;
        #pragma unroll 1
        for (int s = 0; s < 4; s++) {
            float t = t0 + ((s == 0) ? 0.0f : (s == 3 ? DT : 0.5f*DT));

            float rv[28];
            float fv[28];

            // ===== pair loop, streamed Ga_j, j-outer: only r and f =====
            #pragma unroll
            for (int j = 1; j < 8; j++) {
                // full Ue_j broadcast (partner exchange + SEL merge)
                ull p0 = shflx_ull(UeP[j*2]), p1 = shflx_ull(UeP[j*2+1]);
                ull aa[4];
                aa[0] = h ? p0 : UeP[j*2];
                aa[1] = h ? p1 : UeP[j*2+1];
                aa[2] = h ? UeP[j*2]   : p0;
                aa[3] = h ? UeP[j*2+1] : p1;
                // Ga_j = W2a * Ue_j^T  (my half)
                ull ga0, ga1;
                #pragma unroll
                for (int k = 0; k < 8; k++) {
                    ull d = (k & 1) ? dup_hi(aa[k>>1]) : dup_lo(aa[k>>1]);
                    if (k == 0) { ga0 = mul2(d, w2h[0]);        ga1 = mul2(d, w2h[1]); }
                    else        { ga0 = fma2(d, w2h[k*4+0], ga0); ga1 = fma2(d, w2h[k*4+1], ga1); }
                }
                ull vj0 = sv[(j*2)*NT], vj1 = sv[(j*2+1)*NT];
                #pragma unroll
                for (int i = 0; i < j; i++) {
                    ull vi0 = sv[(i*2)*NT], vi1 = sv[(i*2+1)*NT];
                    // r = <Ue_j, v_i> - <Ue_i, v_j>   (full, via half + combine)
                    ull pr = sub2(dot2(UeP[j*2], UeP[j*2+1], vi0, vi1),
                                  dot2(UeP[i*2], UeP[i*2+1], vj0, vj1));
                    float rh = hsum2(pr);
                    rv[TRI(i,j)] = rh + shflx_f(rh);
                    // f = w0a + t*w1a + 0.5*<Ue_i, Ga_j>
                    ull pg = dot2(UeP[i*2], UeP[i*2+1], ga0, ga1);
                    float gh = hsum2(pg);
                    float g  = gh + shflx_f(gh);
                    float w0, w1; unp2(w01[TRI(i,j)], w0, w1);
                    fv[TRI(i,j)] = fmaf(t, w1, fmaf(0.5f, g, w0));
                }
            }

            // ===== fused vel + z rows, kl = Sum_i <z_i, gw_i> (my half) =====
            ull klP = 0ull;
            ull T[16];
            #pragma unroll
            for (int i = 0; i < 8; i++) {
                ull a0, a1, z0, z1;
                #pragma unroll
                for (int j = 0; j < 8; j++) {
                    if (j == i) continue;
                    const bool first = (j == ((i == 0) ? 1 : 0));
                    float f = (i < j) ? fv[TRI(i,j)] : -fv[TRI(j,i)];
                    float r = (i < j) ? rv[TRI(i,j)] : -rv[TRI(j,i)];
                    ull fd = dup_f(f);
                    ull rd = dup_f(r);
                    if (first) {
                        a0 = mul2(fd, UeP[j*2]);     a1 = mul2(fd, UeP[j*2+1]);
                        z0 = mul2(rd, UeP[j*2]);     z1 = mul2(rd, UeP[j*2+1]);
                    } else {
                        a0 = fma2(fd, UeP[j*2], a0); a1 = fma2(fd, UeP[j*2+1], a1);
                        z0 = fma2(rd, UeP[j*2], z0); z1 = fma2(rd, UeP[j*2+1], z1);
                    }
                }
                T[i*2] = a0; T[i*2+1] = a1;
                klP = add2(klP, dot2(z0, z1, sgw[(i*2)*NT], sgw[(i*2+1)*NT]));
            }

            // ===== RK4 stage update (kl kept packed per-half; sign at output) =====
            if (s == 0) {
                laccP = klP;
                const ull hdt = dup_f(0.5f*DT);
                #pragma unroll
                for (int c = 0; c < 16; c++) {
                    sac[c*NT] = T[c];
                    UeP[c] = fma2(hdt, T[c], UeP[c]);
                }
            } else if (s == 1) {
                const ull two = dup_f(2.0f), hdt = dup_f(0.5f*DT);
                laccP = fma2(two, klP, laccP);
                #pragma unroll
                for (int c = 0; c < 16; c++) {
                    sac[c*NT] = fma2(two, T[c], sac[c*NT]);
                    UeP[c] = fma2(hdt, T[c], sub[c*NT]);
                }
            } else if (s == 2) {
                const ull two = dup_f(2.0f), fdt = dup_f(DT);
                laccP = fma2(two, klP, laccP);
                #pragma unroll
                for (int c = 0; c < 16; c++) {
                    sac[c*NT] = fma2(two, T[c], sac[c*NT]);
                    UeP[c] = fma2(fdt, T[c], sub[c*NT]);
                }
            } else {
                const ull d6 = dup_f(DT/6.0f);
                logjP = fma2(d6, add2(laccP, klP), logjP);
                #pragma unroll
                for (int c = 0; c < 16; c++) {
                    ull un = fma2(d6, add2(sac[c*NT], T[c]), sub[c*NT]);
                    UeP[c] = un;
                    sub[c*NT] = un;
                }
            }
        }
    }

    // ---- outputs: U halves, then logj (pair-combined; kl sign gives -0.5) ----
    {
        float* ob = out + (size_t)ge * 64 + h*4;
        #pragma unroll
        for (int r = 0; r < 8; r++) {
            ulonglong2 w; w.x = UeP[r*2]; w.y = UeP[r*2+1];
            *(ulonglong2*)(ob + r*8) = w;
        }
        float lj = hsum2(logjP);
        lj += shflx_f(lj);
        if (h == 0) out[(size_t)B * 64 + ge] = -0.5f * lj;
    }
}

extern "C" void kernel_launch(void* const* d_in, const int* in_sizes, int n_in,
                              void* d_out, int out_size)
{
    const float* U0  = (const float*)d_in[0];
    const float* eps = (const float*)d_in[1];
    const float* W0  = (const float*)d_in[2];
    const float* W1  = (const float*)d_in[3];
    const float* W2  = (const float*)d_in[4];
    float* out = (float*)d_out;

    int B = in_sizes[0] / 64;
    size_t shmem = (size_t)(64 + 4 * 16 * NT) * sizeof(ull);   // ~192.7 KB
    cudaFuncSetAttribute(adj_lie_kernel,
                         cudaFuncAttributeMaxDynamicSharedMemorySize, (int)shmem);
    int grid = (B + NT/2 - 1) / (NT/2);
    adj_lie_kernel<<<grid, NT, shmem>>>(U0, eps, W0, W1, W2, out, B);
}